// round 10
// baseline (speedup 1.0000x reference)
#include <cuda_runtime.h>
#include <cuda_fp16.h>
#include <cstdint>
#include <cstddef>

// Problem dims
#define BB 64
#define NI 1024
#define DI 16
#define NJ 32
#define DJ 32
#define IPW 16                       // i's per WARP in routing passes
#define PASS_GRID_Y (NI / (4 * IPW)) // 16 (4 independent warps per block)

// Scratch (device globals; no dynamic allocation allowed)
__device__ __align__(16) __half g_hat[(size_t)BB * NI * NJ * DJ];  // 128 MB
__device__ __align__(16) float  g_acc[3][BB * NJ * DJ];            // per-iteration accumulators

// ---------- packed f32x2 helpers ----------
__device__ __forceinline__ unsigned long long pack2f(float x, float y) {
    unsigned long long r;
    asm("mov.b64 %0, {%1, %2};" : "=l"(r) : "f"(x), "f"(y));
    return r;
}
__device__ __forceinline__ unsigned long long ffma2(unsigned long long a, unsigned long long b,
                                                    unsigned long long c) {
    unsigned long long d;
    asm("fma.rn.f32x2 %0, %1, %2, %3;" : "=l"(d) : "l"(a), "l"(b), "l"(c));
    return d;
}
__device__ __forceinline__ float2 unpack2f(unsigned long long v) {
    float lo, hi;
    asm("mov.b64 {%0, %1}, %2;" : "=f"(lo), "=f"(hi) : "l"(v));
    return make_float2(lo, hi);
}
__device__ __forceinline__ float2 h2f2(uint32_t u) {
    __half2 h = *reinterpret_cast<__half2*>(&u);
    return __half22float2(h);
}

// ============================================================================
// K1: hat[b,i,j,m] = sum_n W[i,j,n,m] * x[b,i,n], stored fp16.
// grid = NI blocks (one i each), 256 threads; thread t owns jm = 4t..4t+3.
// Blocks 0..767 zero the three acc buffers (768*256 = 3*65536).
// ============================================================================
__global__ __launch_bounds__(256) void k_hat(const float* __restrict__ inp,
                                             const float* __restrict__ W) {
    const int i = blockIdx.x;
    const int t = threadIdx.x;

    if (i < 768) (&g_acc[0][0])[i * 256 + t] = 0.f;

    const int j  = t >> 3;
    const int m0 = (4 * t) & 31;

    const float4* Wp = reinterpret_cast<const float4*>(
        W + ((size_t)i * NJ + j) * (DI * DJ) + m0);
    unsigned long long w01[16], w23[16];
#pragma unroll
    for (int n = 0; n < 16; n++) {
        float4 w = Wp[n * (DJ / 4)];
        w01[n] = pack2f(w.x, w.y);
        w23[n] = pack2f(w.z, w.w);
    }

    // Splatted x table: s_x2[b][n] = (x, x) as a 64-bit value.
    __shared__ __align__(16) float2 s_x2[BB][DI];
    {
        const int b  = t >> 2;               // 0..63
        const int q  = t & 3;                // 0..3 -> n = 4q..4q+3
        float4 v = reinterpret_cast<const float4*>(inp)[((size_t)b * NI + i) * 4 + q];
        s_x2[b][4 * q + 0] = make_float2(v.x, v.x);
        s_x2[b][4 * q + 1] = make_float2(v.y, v.y);
        s_x2[b][4 * q + 2] = make_float2(v.z, v.z);
        s_x2[b][4 * q + 3] = make_float2(v.w, v.w);
    }
    __syncthreads();

#pragma unroll 2
    for (int b = 0; b < BB; b++) {
        unsigned long long a01 = 0ULL, a23 = 0ULL;
#pragma unroll
        for (int n = 0; n < 16; n++) {
            unsigned long long xx =
                *reinterpret_cast<const unsigned long long*>(&s_x2[b][n]);
            a01 = ffma2(xx, w01[n], a01);
            a23 = ffma2(xx, w23[n], a23);
        }
        float2 f01 = unpack2f(a01);
        float2 f23 = unpack2f(a23);
        __half2 h0 = __floats2half2_rn(f01.x, f01.y);
        __half2 h1 = __floats2half2_rn(f23.x, f23.y);
        uint2 st;
        st.x = reinterpret_cast<uint32_t&>(h0);
        st.y = reinterpret_cast<uint32_t&>(h1);
        *reinterpret_cast<uint2*>(&g_hat[((size_t)b * NI + i) * (NJ * DJ) + 4 * t]) = st;
    }
}

// ============================================================================
// Redundant squash of one acc buffer -> this lane's 8-float op slice for
// capsule j, m = 8u..8u+8. 4-lane shuffle reduction (lanes 4g..4g+3 share j).
// ============================================================================
__device__ __forceinline__ void load_op_squash(const float* __restrict__ acc,
                                               int b, int j, int u, float op[8]) {
    const float4* a4 = reinterpret_cast<const float4*>(&acc[(b * NJ + j) * DJ + 8 * u]);
    float4 f0 = a4[0], f1 = a4[1];
    op[0] = f0.x; op[1] = f0.y; op[2] = f0.z; op[3] = f0.w;
    op[4] = f1.x; op[5] = f1.y; op[6] = f1.z; op[7] = f1.w;
    float sq = 0.f;
#pragma unroll
    for (int k = 0; k < 8; k++) sq = fmaf(op[k], op[k], sq);
    sq += __shfl_xor_sync(0xffffffffu, sq, 1);
    sq += __shfl_xor_sync(0xffffffffu, sq, 2);   // full ||s_j||^2 (32 m's)
    float scale = sq / ((1.f + sq) * sqrtf(sq + 1e-7f));
#pragma unroll
    for (int k = 0; k < 8; k++) op[k] *= scale;
}

// ============================================================================
// Routing pass — WARP-INDEPENDENT, zero block barriers.
// Each warp owns IPW consecutive i's of one b. Per row i, the warp loads the
// full 2048-byte row as 4 coalesced LDG.128 (segment s, lane l -> uint4
// s*32+l). Lane l holds, for each s, m-octet u=l&3 of capsule j = s*8 + l/4,
// so ALL 32 j's live inside the warp:
//   logit_j:   per-s 4-lane dot reduction (shfl xor 1,2)
//   softmax:   per-lane sum of its 4 e's, then shfl xor 4,8,16 = exact sum_j
// Next-row prefetch keeps 4 LDG.128 in flight per warp continuously.
// PHASE 0: c = 1/32,                        writes g_acc[0]
// PHASE 1: op = squash(acc0),               writes g_acc[1]
// PHASE 2: op = squash(acc0)+squash(acc1),  writes g_acc[2]
// ============================================================================
template <int PHASE>
__global__ __launch_bounds__(128) void k_pass() {
    const int b = blockIdx.x;
    const int w = threadIdx.x >> 5;
    const int l = threadIdx.x & 31;
    const int u = l & 3;
    const int g = l >> 2;
    const int i0 = (blockIdx.y * 4 + w) * IPW;

    unsigned long long op2[4][4];
    if (PHASE >= 1) {
#pragma unroll
        for (int s = 0; s < 4; s++) {
            float op[8];
            load_op_squash(g_acc[0], b, s * 8 + g, u, op);
            if (PHASE == 2) {
                float op1[8];
                load_op_squash(g_acc[1], b, s * 8 + g, u, op1);
#pragma unroll
                for (int k = 0; k < 8; k++) op[k] += op1[k];
            }
            op2[s][0] = pack2f(op[0], op[1]);
            op2[s][1] = pack2f(op[2], op[3]);
            op2[s][2] = pack2f(op[4], op[5]);
            op2[s][3] = pack2f(op[6], op[7]);
        }
    }

    unsigned long long acc[4][4];
#pragma unroll
    for (int s = 0; s < 4; s++)
#pragma unroll
        for (int k = 0; k < 4; k++) acc[s][k] = 0ULL;

    // Row base: 128 uint4 per row; lane's slot for segment s is [s*32 + l].
    const uint4* p = reinterpret_cast<const uint4*>(
                         g_hat + ((size_t)b * NI + i0) * (NJ * DJ)) + l;

    uint4 cur[4], nxt[4];
#pragma unroll
    for (int s = 0; s < 4; s++) cur[s] = p[s * 32];

    for (int it = 0; it < IPW; it++) {
        const int nx = (it + 1 < IPW) ? (it + 1) : it;
#pragma unroll
        for (int s = 0; s < 4; s++) nxt[s] = p[(size_t)nx * 128 + s * 32];

        // Unpack current row: hf[s][k] = packed f32 pair (2 m's)
        unsigned long long hf[4][4];
#pragma unroll
        for (int s = 0; s < 4; s++) {
            float2 f0 = h2f2(cur[s].x), f1 = h2f2(cur[s].y);
            float2 f2 = h2f2(cur[s].z), f3 = h2f2(cur[s].w);
            hf[s][0] = pack2f(f0.x, f0.y);
            hf[s][1] = pack2f(f1.x, f1.y);
            hf[s][2] = pack2f(f2.x, f2.y);
            hf[s][3] = pack2f(f3.x, f3.y);
        }

        float c[4];
        if (PHASE >= 1) {
            float lg[4];
#pragma unroll
            for (int s = 0; s < 4; s++) {
                unsigned long long l2 = 0ULL;
                l2 = ffma2(op2[s][0], hf[s][0], l2);
                l2 = ffma2(op2[s][1], hf[s][1], l2);
                l2 = ffma2(op2[s][2], hf[s][2], l2);
                l2 = ffma2(op2[s][3], hf[s][3], l2);
                float2 lf = unpack2f(l2);
                float lgt = lf.x + lf.y;
                lgt += __shfl_xor_sync(0xffffffffu, lgt, 1);
                lgt += __shfl_xor_sync(0xffffffffu, lgt, 2);
                lg[s] = lgt;
            }
            float e0 = __expf(lg[0]), e1 = __expf(lg[1]);
            float e2 = __expf(lg[2]), e3 = __expf(lg[3]);
            float tot = e0 + e1 + e2 + e3;       // 4 distinct j's of this lane
            tot += __shfl_xor_sync(0xffffffffu, tot, 4);
            tot += __shfl_xor_sync(0xffffffffu, tot, 8);
            tot += __shfl_xor_sync(0xffffffffu, tot, 16);  // exact sum over 32 j
            float inv = 1.f / tot;
            c[0] = e0 * inv; c[1] = e1 * inv; c[2] = e2 * inv; c[3] = e3 * inv;
        } else {
#pragma unroll
            for (int s = 0; s < 4; s++) c[s] = 1.0f / 32.0f;
        }

#pragma unroll
        for (int s = 0; s < 4; s++) {
            const unsigned long long cc = pack2f(c[s], c[s]);
            acc[s][0] = ffma2(cc, hf[s][0], acc[s][0]);
            acc[s][1] = ffma2(cc, hf[s][1], acc[s][1]);
            acc[s][2] = ffma2(cc, hf[s][2], acc[s][2]);
            acc[s][3] = ffma2(cc, hf[s][3], acc[s][3]);
        }

#pragma unroll
        for (int s = 0; s < 4; s++) cur[s] = nxt[s];
    }

#pragma unroll
    for (int s = 0; s < 4; s++) {
        float* ap = &g_acc[PHASE][(b * NJ + s * 8 + g) * DJ + 8 * u];
        float2 v;
        v = unpack2f(acc[s][0]); atomicAdd(ap + 0, v.x); atomicAdd(ap + 1, v.y);
        v = unpack2f(acc[s][1]); atomicAdd(ap + 2, v.x); atomicAdd(ap + 3, v.y);
        v = unpack2f(acc[s][2]); atomicAdd(ap + 4, v.x); atomicAdd(ap + 5, v.y);
        v = unpack2f(acc[s][3]); atomicAdd(ap + 6, v.x); atomicAdd(ap + 7, v.y);
    }
}

// ============================================================================
// Final squash: out = squash(g_acc[2]). grid = BB, 1024 threads; warp=j, lane=m.
// ============================================================================
__global__ void k_squash_final(float* __restrict__ out) {
    const int b = blockIdx.x;
    const int j = threadIdx.x >> 5;
    const int m = threadIdx.x & 31;
    const int idx = (b * NJ + j) * DJ + m;
    float s = g_acc[2][idx];
    float sq = s * s;
#pragma unroll
    for (int o = 16; o > 0; o >>= 1)
        sq += __shfl_xor_sync(0xffffffffu, sq, o);
    float scale = sq / ((1.f + sq) * sqrtf(sq + 1e-7f));
    out[idx] = scale * s;
}

// ============================================================================
extern "C" void kernel_launch(void* const* d_in, const int* in_sizes, int n_in,
                              void* d_out, int out_size) {
    const float* inp = (const float*)d_in[0];  // [64, 1024, 16]
    const float* W   = (const float*)d_in[1];  // [1024, 32, 16, 32]
    float* out = (float*)d_out;                // [64, 32, 32]

    const dim3 passGrid(BB, PASS_GRID_Y);

    k_hat<<<NI, 256>>>(inp, W);

    k_pass<0><<<passGrid, 128>>>();
    k_pass<1><<<passGrid, 128>>>();
    k_pass<2><<<passGrid, 128>>>();

    k_squash_final<<<BB, 1024>>>(out);
}

// round 11
// speedup vs baseline: 1.1025x; 1.1025x over previous
#include <cuda_runtime.h>
#include <cuda_fp16.h>
#include <cstdint>
#include <cstddef>

// Problem dims
#define BB 64
#define NI 1024
#define DI 16
#define NJ 32
#define DJ 32
#define IPW 32                      // i's per block in routing passes
#define PASS_GRID_Y (NI / IPW)      // 32
#define BCHUNK 32                   // b's per phase-chunk (64 MB of hat < 126 MB L2)

// Scratch (device globals; no dynamic allocation allowed)
__device__ __align__(16) __half g_hat[(size_t)BB * NI * NJ * DJ];  // 128 MB
__device__ __align__(16) float  g_acc[3][BB * NJ * DJ];            // per-iteration accumulators

// ---------- packed f32x2 helpers ----------
__device__ __forceinline__ unsigned long long pack2f(float x, float y) {
    unsigned long long r;
    asm("mov.b64 %0, {%1, %2};" : "=l"(r) : "f"(x), "f"(y));
    return r;
}
__device__ __forceinline__ unsigned long long ffma2(unsigned long long a, unsigned long long b,
                                                    unsigned long long c) {
    unsigned long long d;
    asm("fma.rn.f32x2 %0, %1, %2, %3;" : "=l"(d) : "l"(a), "l"(b), "l"(c));
    return d;
}
__device__ __forceinline__ float2 unpack2f(unsigned long long v) {
    float lo, hi;
    asm("mov.b64 {%0, %1}, %2;" : "=f"(lo), "=f"(hi) : "l"(v));
    return make_float2(lo, hi);
}
__device__ __forceinline__ float2 h2f2(uint32_t u) {
    __half2 h = *reinterpret_cast<__half2*>(&u);
    return __half22float2(h);
}

// ============================================================================
// K1: hat[b,i,j,m] = sum_n W[i,j,n,m] * x[b,i,n], stored fp16.
// grid = NI blocks (one i each), 256 threads; thread t owns jm = 4t..4t+3.
// Blocks 0..767 zero the three acc buffers (768*256 = 3*65536).
// ============================================================================
__global__ __launch_bounds__(256) void k_hat(const float* __restrict__ inp,
                                             const float* __restrict__ W) {
    const int i = blockIdx.x;
    const int t = threadIdx.x;

    if (i < 768) (&g_acc[0][0])[i * 256 + t] = 0.f;

    const int j  = t >> 3;
    const int m0 = (4 * t) & 31;

    const float4* Wp = reinterpret_cast<const float4*>(
        W + ((size_t)i * NJ + j) * (DI * DJ) + m0);
    unsigned long long w01[16], w23[16];
#pragma unroll
    for (int n = 0; n < 16; n++) {
        float4 w = Wp[n * (DJ / 4)];
        w01[n] = pack2f(w.x, w.y);
        w23[n] = pack2f(w.z, w.w);
    }

    // Splatted x table: s_x2[b][n] = (x, x) as a 64-bit value.
    __shared__ __align__(16) float2 s_x2[BB][DI];
    {
        const int b  = t >> 2;               // 0..63
        const int q  = t & 3;                // 0..3 -> n = 4q..4q+3
        float4 v = reinterpret_cast<const float4*>(inp)[((size_t)b * NI + i) * 4 + q];
        s_x2[b][4 * q + 0] = make_float2(v.x, v.x);
        s_x2[b][4 * q + 1] = make_float2(v.y, v.y);
        s_x2[b][4 * q + 2] = make_float2(v.z, v.z);
        s_x2[b][4 * q + 3] = make_float2(v.w, v.w);
    }
    __syncthreads();

#pragma unroll 2
    for (int b = 0; b < BB; b++) {
        unsigned long long a01 = 0ULL, a23 = 0ULL;
#pragma unroll
        for (int n = 0; n < 16; n++) {
            unsigned long long xx =
                *reinterpret_cast<const unsigned long long*>(&s_x2[b][n]);
            a01 = ffma2(xx, w01[n], a01);
            a23 = ffma2(xx, w23[n], a23);
        }
        float2 f01 = unpack2f(a01);
        float2 f23 = unpack2f(a23);
        __half2 h0 = __floats2half2_rn(f01.x, f01.y);
        __half2 h1 = __floats2half2_rn(f23.x, f23.y);
        uint2 st;
        st.x = reinterpret_cast<uint32_t&>(h0);
        st.y = reinterpret_cast<uint32_t&>(h1);
        *reinterpret_cast<uint2*>(&g_hat[((size_t)b * NI + i) * (NJ * DJ) + 4 * t]) = st;
    }
}

// ============================================================================
// Redundant per-block squash of one acc buffer -> this thread's 8-float op
// slice (j = its j, m = 8u..8u+8). 4-lane shuffle reduction, no smem/barrier.
// ============================================================================
__device__ __forceinline__ void load_op_squash(const float* __restrict__ acc,
                                               int b, int j, int u, float op[8]) {
    const float4* a4 = reinterpret_cast<const float4*>(&acc[(b * NJ + j) * DJ + 8 * u]);
    float4 f0 = a4[0], f1 = a4[1];
    op[0] = f0.x; op[1] = f0.y; op[2] = f0.z; op[3] = f0.w;
    op[4] = f1.x; op[5] = f1.y; op[6] = f1.z; op[7] = f1.w;
    float sq = 0.f;
#pragma unroll
    for (int k = 0; k < 8; k++) sq = fmaf(op[k], op[k], sq);
    sq += __shfl_xor_sync(0xffffffffu, sq, 1);
    sq += __shfl_xor_sync(0xffffffffu, sq, 2);   // full ||s_j||^2 (32 m's)
    float scale = sq / ((1.f + sq) * sqrtf(sq + 1e-7f));
#pragma unroll
    for (int k = 0; k < 8; k++) op[k] *= scale;
}

// ============================================================================
// Routing pass (R8 block-cooperative design + b-chunking + depth-4 prefetch).
// 128-thread block (4 warps) processes one i per step; warp w lane l loads
// uint4 (w*32+l) of the 2048-byte row (perfectly coalesced). Lane owns
// j = w*8 + l/4, m = 8(l&3)..+8.
// Depth-4 prefetch: consume buf[it&3] into regs FIRST, then refill that slot
// with row it+4 (4 outstanding LDG.128 per warp, no extra registers).
// PHASE 0: c = 1/32 uniform,                     writes g_acc[0]
// PHASE 1: op = squash(acc0),                    writes g_acc[1]
// PHASE 2: op = squash(acc0)+squash(acc1),       writes g_acc[2]
// Chunked over b (b = b0 + blockIdx.x, 32 b's per launch) so that phases 1,2
// of a chunk re-read a 64 MB hat working set that is resident in L2.
// ============================================================================
template <int PHASE>
__global__ __launch_bounds__(128) void k_pass(int b0) {
    const int b = b0 + blockIdx.x;
    const int w = threadIdx.x >> 5;
    const int l = threadIdx.x & 31;
    const int u = l & 3;
    const int j = w * 8 + (l >> 2);
    const int i0 = blockIdx.y * IPW;

    unsigned long long op2[4];
    if (PHASE >= 1) {
        float op[8];
        load_op_squash(g_acc[0], b, j, u, op);
        if (PHASE == 2) {
            float op1[8];
            load_op_squash(g_acc[1], b, j, u, op1);
#pragma unroll
            for (int k = 0; k < 8; k++) op[k] += op1[k];
        }
        op2[0] = pack2f(op[0], op[1]);
        op2[1] = pack2f(op[2], op[3]);
        op2[2] = pack2f(op[4], op[5]);
        op2[3] = pack2f(op[6], op[7]);
    }

    __shared__ float s_red[2][4];

    unsigned long long a0 = 0ULL, a1 = 0ULL, a2 = 0ULL, a3 = 0ULL;

    const uint4* p = reinterpret_cast<const uint4*>(
                         g_hat + ((size_t)b * NI + i0) * (NJ * DJ)) + (w * 32 + l);

    uint4 buf[4];
    buf[0] = p[0];
    buf[1] = p[128];
    buf[2] = p[256];
    buf[3] = p[384];

#pragma unroll 4
    for (int it = 0; it < IPW; it++) {
        uint4 cur = buf[it & 3];
        const int pf = (it + 4 < IPW) ? (it + 4) : (IPW - 1);
        buf[it & 3] = p[(size_t)pf * 128];          // depth-4: refill freed slot

        float2 f0 = h2f2(cur.x), f1 = h2f2(cur.y), f2 = h2f2(cur.z), f3 = h2f2(cur.w);
        unsigned long long hf0 = pack2f(f0.x, f0.y);
        unsigned long long hf1 = pack2f(f1.x, f1.y);
        unsigned long long hf2 = pack2f(f2.x, f2.y);
        unsigned long long hf3 = pack2f(f3.x, f3.y);

        float c;
        if (PHASE >= 1) {
            unsigned long long l2 = 0ULL;
            l2 = ffma2(op2[0], hf0, l2);
            l2 = ffma2(op2[1], hf1, l2);
            l2 = ffma2(op2[2], hf2, l2);
            l2 = ffma2(op2[3], hf3, l2);
            float2 lf = unpack2f(l2);
            float logit = lf.x + lf.y;
            logit += __shfl_xor_sync(0xffffffffu, logit, 1);
            logit += __shfl_xor_sync(0xffffffffu, logit, 2);
            float e = __expf(logit);           // logits bounded; no max-sub needed
            float se = e;
            se += __shfl_xor_sync(0xffffffffu, se, 4);
            se += __shfl_xor_sync(0xffffffffu, se, 8);
            se += __shfl_xor_sync(0xffffffffu, se, 16);   // = 4 * sum_{j in warp} e_j
            if (l == 0) s_red[it & 1][w] = se;
            __syncthreads();
            float tot = s_red[it & 1][0] + s_red[it & 1][1] +
                        s_red[it & 1][2] + s_red[it & 1][3];
            c = 4.f * e / tot;                 // tot = 4 * sum_all e_j
        } else {
            c = 1.0f / 32.0f;
        }

        const unsigned long long cc = pack2f(c, c);
        a0 = ffma2(cc, hf0, a0);
        a1 = ffma2(cc, hf1, a1);
        a2 = ffma2(cc, hf2, a2);
        a3 = ffma2(cc, hf3, a3);
    }

    float* ap = &g_acc[PHASE][(b * NJ + j) * DJ + 8 * u];
    float2 v;
    v = unpack2f(a0); atomicAdd(ap + 0, v.x); atomicAdd(ap + 1, v.y);
    v = unpack2f(a1); atomicAdd(ap + 2, v.x); atomicAdd(ap + 3, v.y);
    v = unpack2f(a2); atomicAdd(ap + 4, v.x); atomicAdd(ap + 5, v.y);
    v = unpack2f(a3); atomicAdd(ap + 6, v.x); atomicAdd(ap + 7, v.y);
}

// ============================================================================
// Final squash: out = squash(g_acc[2]). grid = BB, 1024 threads; warp=j, lane=m.
// ============================================================================
__global__ void k_squash_final(float* __restrict__ out) {
    const int b = blockIdx.x;
    const int j = threadIdx.x >> 5;
    const int m = threadIdx.x & 31;
    const int idx = (b * NJ + j) * DJ + m;
    float s = g_acc[2][idx];
    float sq = s * s;
#pragma unroll
    for (int o = 16; o > 0; o >>= 1)
        sq += __shfl_xor_sync(0xffffffffu, sq, o);
    float scale = sq / ((1.f + sq) * sqrtf(sq + 1e-7f));
    out[idx] = scale * s;
}

// ============================================================================
extern "C" void kernel_launch(void* const* d_in, const int* in_sizes, int n_in,
                              void* d_out, int out_size) {
    const float* inp = (const float*)d_in[0];  // [64, 1024, 16]
    const float* W   = (const float*)d_in[1];  // [1024, 32, 16, 32]
    float* out = (float*)d_out;                // [64, 32, 32]

    const dim3 passGrid(BCHUNK, PASS_GRID_Y);

    k_hat<<<NI, 256>>>(inp, W);

    // Per-chunk phase pipeline: phases 1,2 re-read the chunk's 64 MB hat
    // working set while it is still L2-resident.
    for (int b0 = 0; b0 < BB; b0 += BCHUNK) {
        k_pass<0><<<passGrid, 128>>>(b0);
        k_pass<1><<<passGrid, 128>>>(b0);
        k_pass<2><<<passGrid, 128>>>(b0);
    }

    k_squash_final<<<BB, 1024>>>(out);
}

// round 13
// speedup vs baseline: 1.3031x; 1.1820x over previous
#include <cuda_runtime.h>
#include <cuda_fp16.h>
#include <cstdint>
#include <cstddef>

// Problem dims
#define BB 64
#define NI 1024
#define DI 16
#define NJ 32
#define DJ 32
#define IPW 64                      // i's per block in routing passes
#define PASS_GRID_Y (NI / IPW)      // 16  -> grid 64*16 = 1024 blocks = ONE wave

// Scratch (device globals; no dynamic allocation allowed)
__device__ __align__(16) __half g_hat[(size_t)BB * NI * NJ * DJ];  // 128 MB
__device__ __align__(16) float  g_acc[3][BB * NJ * DJ];            // per-iteration accumulators

// ---------- packed f32x2 helpers ----------
__device__ __forceinline__ unsigned long long pack2f(float x, float y) {
    unsigned long long r;
    asm("mov.b64 %0, {%1, %2};" : "=l"(r) : "f"(x), "f"(y));
    return r;
}
__device__ __forceinline__ unsigned long long ffma2(unsigned long long a, unsigned long long b,
                                                    unsigned long long c) {
    unsigned long long d;
    asm("fma.rn.f32x2 %0, %1, %2, %3;" : "=l"(d) : "l"(a), "l"(b), "l"(c));
    return d;
}
__device__ __forceinline__ float2 unpack2f(unsigned long long v) {
    float lo, hi;
    asm("mov.b64 {%0, %1}, %2;" : "=f"(lo), "=f"(hi) : "l"(v));
    return make_float2(lo, hi);
}
__device__ __forceinline__ float2 h2f2(uint32_t u) {
    __half2 h = *reinterpret_cast<__half2*>(&u);
    return __half22float2(h);
}

// ============================================================================
// K1: hat[b,i,j,m] = sum_n W[i,j,n,m] * x[b,i,n], stored fp16.
// grid = NI blocks (one i each), 256 threads; thread t owns jm = 4t..4t+3.
// Blocks 0..767 zero the three acc buffers (768*256 = 3*65536).
// ============================================================================
__global__ __launch_bounds__(256) void k_hat(const float* __restrict__ inp,
                                             const float* __restrict__ W) {
    const int i = blockIdx.x;
    const int t = threadIdx.x;

    if (i < 768) (&g_acc[0][0])[i * 256 + t] = 0.f;

    const int j  = t >> 3;
    const int m0 = (4 * t) & 31;

    const float4* Wp = reinterpret_cast<const float4*>(
        W + ((size_t)i * NJ + j) * (DI * DJ) + m0);
    unsigned long long w01[16], w23[16];
#pragma unroll
    for (int n = 0; n < 16; n++) {
        float4 w = Wp[n * (DJ / 4)];
        w01[n] = pack2f(w.x, w.y);
        w23[n] = pack2f(w.z, w.w);
    }

    // Splatted x table: s_x2[b][n] = (x, x) as a 64-bit value.
    __shared__ __align__(16) float2 s_x2[BB][DI];
    {
        const int b  = t >> 2;               // 0..63
        const int q  = t & 3;                // 0..3 -> n = 4q..4q+3
        float4 v = reinterpret_cast<const float4*>(inp)[((size_t)b * NI + i) * 4 + q];
        s_x2[b][4 * q + 0] = make_float2(v.x, v.x);
        s_x2[b][4 * q + 1] = make_float2(v.y, v.y);
        s_x2[b][4 * q + 2] = make_float2(v.z, v.z);
        s_x2[b][4 * q + 3] = make_float2(v.w, v.w);
    }
    __syncthreads();

#pragma unroll 2
    for (int b = 0; b < BB; b++) {
        unsigned long long a01 = 0ULL, a23 = 0ULL;
#pragma unroll
        for (int n = 0; n < 16; n++) {
            unsigned long long xx =
                *reinterpret_cast<const unsigned long long*>(&s_x2[b][n]);
            a01 = ffma2(xx, w01[n], a01);
            a23 = ffma2(xx, w23[n], a23);
        }
        float2 f01 = unpack2f(a01);
        float2 f23 = unpack2f(a23);
        __half2 h0 = __floats2half2_rn(f01.x, f01.y);
        __half2 h1 = __floats2half2_rn(f23.x, f23.y);
        uint2 st;
        st.x = reinterpret_cast<uint32_t&>(h0);
        st.y = reinterpret_cast<uint32_t&>(h1);
        *reinterpret_cast<uint2*>(&g_hat[((size_t)b * NI + i) * (NJ * DJ) + 4 * t]) = st;
    }
}

// ============================================================================
// Redundant per-block squash of one acc buffer -> this thread's 8-float op
// slice (j = its j, m = 8u..8u+8). 4-lane shuffle reduction, no smem/barrier.
// ============================================================================
__device__ __forceinline__ void load_op_squash(const float* __restrict__ acc,
                                               int b, int j, int u, float op[8]) {
    const float4* a4 = reinterpret_cast<const float4*>(&acc[(b * NJ + j) * DJ + 8 * u]);
    float4 f0 = a4[0], f1 = a4[1];
    op[0] = f0.x; op[1] = f0.y; op[2] = f0.z; op[3] = f0.w;
    op[4] = f1.x; op[5] = f1.y; op[6] = f1.z; op[7] = f1.w;
    float sq = 0.f;
#pragma unroll
    for (int k = 0; k < 8; k++) sq = fmaf(op[k], op[k], sq);
    sq += __shfl_xor_sync(0xffffffffu, sq, 1);
    sq += __shfl_xor_sync(0xffffffffu, sq, 2);   // full ||s_j||^2 (32 m's)
    float scale = sq / ((1.f + sq) * sqrtf(sq + 1e-7f));
#pragma unroll
    for (int k = 0; k < 8; k++) op[k] *= scale;
}

// ============================================================================
// Routing pass (R8 design, IPW=64 -> single wave of 1024 blocks).
// 128-thread block (4 warps) processes one i per step; warp w lane l loads
// uint4 (w*32+l) of the 2048-byte row (perfectly coalesced). Lane owns
// j = w*8 + l/4, m = 8(l&3)..+8.
// Depth-4 prefetch: consume buf[it&3] into regs FIRST, then refill that slot
// with row it+4 (4 outstanding LDG.128 per warp, no extra registers).
// PHASE 0: c = 1/32 uniform,                     writes g_acc[0]
// PHASE 1: op = squash(acc0),                    writes g_acc[1]
// PHASE 2: op = squash(acc0)+squash(acc1),       writes g_acc[2]
// Softmax denominator crosses warps via parity-double-buffered smem + 1 BAR/i.
// ============================================================================
template <int PHASE>
__global__ __launch_bounds__(128) void k_pass() {
    const int b = blockIdx.x;
    const int w = threadIdx.x >> 5;
    const int l = threadIdx.x & 31;
    const int u = l & 3;
    const int j = w * 8 + (l >> 2);
    const int i0 = blockIdx.y * IPW;

    unsigned long long op2[4];
    if (PHASE >= 1) {
        float op[8];
        load_op_squash(g_acc[0], b, j, u, op);
        if (PHASE == 2) {
            float op1[8];
            load_op_squash(g_acc[1], b, j, u, op1);
#pragma unroll
            for (int k = 0; k < 8; k++) op[k] += op1[k];
        }
        op2[0] = pack2f(op[0], op[1]);
        op2[1] = pack2f(op[2], op[3]);
        op2[2] = pack2f(op[4], op[5]);
        op2[3] = pack2f(op[6], op[7]);
    }

    __shared__ float s_red[2][4];

    unsigned long long a0 = 0ULL, a1 = 0ULL, a2 = 0ULL, a3 = 0ULL;

    const uint4* p = reinterpret_cast<const uint4*>(
                         g_hat + ((size_t)b * NI + i0) * (NJ * DJ)) + (w * 32 + l);

    uint4 buf[4];
    buf[0] = p[0];
    buf[1] = p[128];
    buf[2] = p[256];
    buf[3] = p[384];

#pragma unroll 4
    for (int it = 0; it < IPW; it++) {
        uint4 cur = buf[it & 3];
        const int pf = (it + 4 < IPW) ? (it + 4) : (IPW - 1);
        buf[it & 3] = p[(size_t)pf * 128];          // depth-4: refill freed slot

        float2 f0 = h2f2(cur.x), f1 = h2f2(cur.y), f2 = h2f2(cur.z), f3 = h2f2(cur.w);
        unsigned long long hf0 = pack2f(f0.x, f0.y);
        unsigned long long hf1 = pack2f(f1.x, f1.y);
        unsigned long long hf2 = pack2f(f2.x, f2.y);
        unsigned long long hf3 = pack2f(f3.x, f3.y);

        float c;
        if (PHASE >= 1) {
            unsigned long long l2 = 0ULL;
            l2 = ffma2(op2[0], hf0, l2);
            l2 = ffma2(op2[1], hf1, l2);
            l2 = ffma2(op2[2], hf2, l2);
            l2 = ffma2(op2[3], hf3, l2);
            float2 lf = unpack2f(l2);
            float logit = lf.x + lf.y;
            logit += __shfl_xor_sync(0xffffffffu, logit, 1);
            logit += __shfl_xor_sync(0xffffffffu, logit, 2);
            float e = __expf(logit);           // logits bounded; no max-sub needed
            float se = e;
            se += __shfl_xor_sync(0xffffffffu, se, 4);
            se += __shfl_xor_sync(0xffffffffu, se, 8);
            se += __shfl_xor_sync(0xffffffffu, se, 16);   // = 4 * sum_{j in warp} e_j
            if (l == 0) s_red[it & 1][w] = se;
            __syncthreads();
            float tot = s_red[it & 1][0] + s_red[it & 1][1] +
                        s_red[it & 1][2] + s_red[it & 1][3];
            c = 4.f * e / tot;                 // tot = 4 * sum_all e_j
        } else {
            c = 1.0f / 32.0f;
        }

        const unsigned long long cc = pack2f(c, c);
        a0 = ffma2(cc, hf0, a0);
        a1 = ffma2(cc, hf1, a1);
        a2 = ffma2(cc, hf2, a2);
        a3 = ffma2(cc, hf3, a3);
    }

    float* ap = &g_acc[PHASE][(b * NJ + j) * DJ + 8 * u];
    float2 v;
    v = unpack2f(a0); atomicAdd(ap + 0, v.x); atomicAdd(ap + 1, v.y);
    v = unpack2f(a1); atomicAdd(ap + 2, v.x); atomicAdd(ap + 3, v.y);
    v = unpack2f(a2); atomicAdd(ap + 4, v.x); atomicAdd(ap + 5, v.y);
    v = unpack2f(a3); atomicAdd(ap + 6, v.x); atomicAdd(ap + 7, v.y);
}

// ============================================================================
// Final squash: out = squash(g_acc[2]). grid = BB, 1024 threads; warp=j, lane=m.
// ============================================================================
__global__ void k_squash_final(float* __restrict__ out) {
    const int b = blockIdx.x;
    const int j = threadIdx.x >> 5;
    const int m = threadIdx.x & 31;
    const int idx = (b * NJ + j) * DJ + m;
    float s = g_acc[2][idx];
    float sq = s * s;
#pragma unroll
    for (int o = 16; o > 0; o >>= 1)
        sq += __shfl_xor_sync(0xffffffffu, sq, o);
    float scale = sq / ((1.f + sq) * sqrtf(sq + 1e-7f));
    out[idx] = scale * s;
}

// ============================================================================
extern "C" void kernel_launch(void* const* d_in, const int* in_sizes, int n_in,
                              void* d_out, int out_size) {
    const float* inp = (const float*)d_in[0];  // [64, 1024, 16]
    const float* W   = (const float*)d_in[1];  // [1024, 32, 16, 32]
    float* out = (float*)d_out;                // [64, 32, 32]

    const dim3 passGrid(BB, PASS_GRID_Y);

    k_hat<<<NI, 256>>>(inp, W);

    k_pass<0><<<passGrid, 128>>>();
    k_pass<1><<<passGrid, 128>>>();
    k_pass<2><<<passGrid, 128>>>();

    k_squash_final<<<BB, 1024>>>(out);
}

// round 15
// speedup vs baseline: 1.3521x; 1.0376x over previous
#include <cuda_runtime.h>
#include <cuda_fp16.h>
#include <cstdint>
#include <cstddef>

// Problem dims
#define BB 64
#define NI 1024
#define DI 16
#define NJ 32
#define DJ 32
#define IPW 64                      // i's per block in routing passes
#define PASS_GRID_Y (NI / IPW)      // 16  -> grid 64*16 = 1024 blocks = ONE wave

// Scratch (device globals; no dynamic allocation allowed)
__device__ __align__(16) __half g_hat[(size_t)BB * NI * NJ * DJ];  // 128 MB
__device__ __align__(16) float  g_acc[3][BB * NJ * DJ];            // per-iteration accumulators

// ---------- packed f32x2 helpers ----------
__device__ __forceinline__ unsigned long long pack2f(float x, float y) {
    unsigned long long r;
    asm("mov.b64 %0, {%1, %2};" : "=l"(r) : "f"(x), "f"(y));
    return r;
}
__device__ __forceinline__ unsigned long long ffma2(unsigned long long a, unsigned long long b,
                                                    unsigned long long c) {
    unsigned long long d;
    asm("fma.rn.f32x2 %0, %1, %2, %3;" : "=l"(d) : "l"(a), "l"(b), "l"(c));
    return d;
}
__device__ __forceinline__ float2 unpack2f(unsigned long long v) {
    float lo, hi;
    asm("mov.b64 {%0, %1}, %2;" : "=f"(lo), "=f"(hi) : "l"(v));
    return make_float2(lo, hi);
}
__device__ __forceinline__ float2 h2f2(uint32_t u) {
    __half2 h = *reinterpret_cast<__half2*>(&u);
    return __half22float2(h);
}

// ============================================================================
// K1: hat[b,i,j,m] = sum_n W[i,j,n,m] * x[b,i,n], stored fp16.
// grid = NI blocks (one i each), 256 threads; thread t owns jm = 4t..4t+3.
// Blocks 0..767 zero the three acc buffers (768*256 = 3*65536).
// ============================================================================
__global__ __launch_bounds__(256) void k_hat(const float* __restrict__ inp,
                                             const float* __restrict__ W) {
    const int i = blockIdx.x;
    const int t = threadIdx.x;

    if (i < 768) (&g_acc[0][0])[i * 256 + t] = 0.f;

    const int j  = t >> 3;
    const int m0 = (4 * t) & 31;

    const float4* Wp = reinterpret_cast<const float4*>(
        W + ((size_t)i * NJ + j) * (DI * DJ) + m0);
    unsigned long long w01[16], w23[16];
#pragma unroll
    for (int n = 0; n < 16; n++) {
        float4 w = Wp[n * (DJ / 4)];
        w01[n] = pack2f(w.x, w.y);
        w23[n] = pack2f(w.z, w.w);
    }

    // Splatted x table: s_x2[b][n] = (x, x) as a 64-bit value.
    __shared__ __align__(16) float2 s_x2[BB][DI];
    {
        const int b  = t >> 2;               // 0..63
        const int q  = t & 3;                // 0..3 -> n = 4q..4q+3
        float4 v = reinterpret_cast<const float4*>(inp)[((size_t)b * NI + i) * 4 + q];
        s_x2[b][4 * q + 0] = make_float2(v.x, v.x);
        s_x2[b][4 * q + 1] = make_float2(v.y, v.y);
        s_x2[b][4 * q + 2] = make_float2(v.z, v.z);
        s_x2[b][4 * q + 3] = make_float2(v.w, v.w);
    }
    __syncthreads();

#pragma unroll 2
    for (int b = 0; b < BB; b++) {
        unsigned long long a01 = 0ULL, a23 = 0ULL;
#pragma unroll
        for (int n = 0; n < 16; n++) {
            unsigned long long xx =
                *reinterpret_cast<const unsigned long long*>(&s_x2[b][n]);
            a01 = ffma2(xx, w01[n], a01);
            a23 = ffma2(xx, w23[n], a23);
        }
        float2 f01 = unpack2f(a01);
        float2 f23 = unpack2f(a23);
        __half2 h0 = __floats2half2_rn(f01.x, f01.y);
        __half2 h1 = __floats2half2_rn(f23.x, f23.y);
        uint2 st;
        st.x = reinterpret_cast<uint32_t&>(h0);
        st.y = reinterpret_cast<uint32_t&>(h1);
        *reinterpret_cast<uint2*>(&g_hat[((size_t)b * NI + i) * (NJ * DJ) + 4 * t]) = st;
    }
}

// ============================================================================
// Redundant per-block squash of one acc buffer -> this thread's 8-float op
// slice (j = its j, m = 8u..8u+8). 4-lane shuffle reduction, no smem/barrier.
// ============================================================================
__device__ __forceinline__ void load_op_squash(const float* __restrict__ acc,
                                               int b, int j, int u, float op[8]) {
    const float4* a4 = reinterpret_cast<const float4*>(&acc[(b * NJ + j) * DJ + 8 * u]);
    float4 f0 = a4[0], f1 = a4[1];
    op[0] = f0.x; op[1] = f0.y; op[2] = f0.z; op[3] = f0.w;
    op[4] = f1.x; op[5] = f1.y; op[6] = f1.z; op[7] = f1.w;
    float sq = 0.f;
#pragma unroll
    for (int k = 0; k < 8; k++) sq = fmaf(op[k], op[k], sq);
    sq += __shfl_xor_sync(0xffffffffu, sq, 1);
    sq += __shfl_xor_sync(0xffffffffu, sq, 2);   // full ||s_j||^2 (32 m's)
    float scale = sq / ((1.f + sq) * sqrtf(sq + 1e-7f));
#pragma unroll
    for (int k = 0; k < 8; k++) op[k] *= scale;
}

// ============================================================================
// Routing pass (R13 design + 2 rows per barrier round).
// 128-thread block (4 warps); warp w lane l loads uint4 (w*32+l) of each
// 2048-byte row (perfectly coalesced). Lane owns j = w*8 + l/4, m = 8(l&3)..+8.
// Per super-iteration: rows (it, it+1) processed together -> ONE __syncthreads
// serves both rows' softmax denominators; refills for rows it+4,it+5 issued
// up front (used two super-iterations later -> 2 LDG.128 always in flight).
// PHASE 0: c = 1/32 uniform,                     writes g_acc[0]
// PHASE 1: op = squash(acc0),                    writes g_acc[1]
// PHASE 2: op = squash(acc0)+squash(acc1),       writes g_acc[2]
// ============================================================================
template <int PHASE>
__global__ __launch_bounds__(128, 7) void k_pass() {
    const int b = blockIdx.x;
    const int w = threadIdx.x >> 5;
    const int l = threadIdx.x & 31;
    const int u = l & 3;
    const int j = w * 8 + (l >> 2);
    const int i0 = blockIdx.y * IPW;

    unsigned long long op2[4];
    if (PHASE >= 1) {
        float op[8];
        load_op_squash(g_acc[0], b, j, u, op);
        if (PHASE == 2) {
            float op1[8];
            load_op_squash(g_acc[1], b, j, u, op1);
#pragma unroll
            for (int k = 0; k < 8; k++) op[k] += op1[k];
        }
        op2[0] = pack2f(op[0], op[1]);
        op2[1] = pack2f(op[2], op[3]);
        op2[2] = pack2f(op[4], op[5]);
        op2[3] = pack2f(op[6], op[7]);
    }

    __shared__ float s_red[2][2][4];   // [parity][row-in-pair][warp]

    unsigned long long a0 = 0ULL, a1 = 0ULL, a2 = 0ULL, a3 = 0ULL;

    const uint4* p = reinterpret_cast<const uint4*>(
                         g_hat + ((size_t)b * NI + i0) * (NJ * DJ)) + (w * 32 + l);

    uint4 buf[4];
    buf[0] = p[0];
    buf[1] = p[128];
    buf[2] = p[256];
    buf[3] = p[384];

#pragma unroll 2
    for (int it = 0; it < IPW; it += 2) {
        const int s0 = it & 3, s1 = (it + 1) & 3;
        uint4 curA = buf[s0];
        uint4 curB = buf[s1];
        // Refill freed slots with rows it+4, it+5 (consumed 2 super-iters later).
        const int pfA = min(it + 4, IPW - 1);
        const int pfB = min(it + 5, IPW - 1);
        buf[s0] = p[(size_t)pfA * 128];
        buf[s1] = p[(size_t)pfB * 128];

        float2 fA0 = h2f2(curA.x), fA1 = h2f2(curA.y), fA2 = h2f2(curA.z), fA3 = h2f2(curA.w);
        unsigned long long hA0 = pack2f(fA0.x, fA0.y);
        unsigned long long hA1 = pack2f(fA1.x, fA1.y);
        unsigned long long hA2 = pack2f(fA2.x, fA2.y);
        unsigned long long hA3 = pack2f(fA3.x, fA3.y);
        float2 fB0 = h2f2(curB.x), fB1 = h2f2(curB.y), fB2 = h2f2(curB.z), fB3 = h2f2(curB.w);
        unsigned long long hB0 = pack2f(fB0.x, fB0.y);
        unsigned long long hB1 = pack2f(fB1.x, fB1.y);
        unsigned long long hB2 = pack2f(fB2.x, fB2.y);
        unsigned long long hB3 = pack2f(fB3.x, fB3.y);

        float cA, cB;
        if (PHASE >= 1) {
            const int par = (it >> 1) & 1;
            unsigned long long lA = 0ULL, lB = 0ULL;
            lA = ffma2(op2[0], hA0, lA);
            lA = ffma2(op2[1], hA1, lA);
            lA = ffma2(op2[2], hA2, lA);
            lA = ffma2(op2[3], hA3, lA);
            lB = ffma2(op2[0], hB0, lB);
            lB = ffma2(op2[1], hB1, lB);
            lB = ffma2(op2[2], hB2, lB);
            lB = ffma2(op2[3], hB3, lB);
            float2 la = unpack2f(lA), lb = unpack2f(lB);
            float logitA = la.x + la.y;
            float logitB = lb.x + lb.y;
            logitA += __shfl_xor_sync(0xffffffffu, logitA, 1);
            logitB += __shfl_xor_sync(0xffffffffu, logitB, 1);
            logitA += __shfl_xor_sync(0xffffffffu, logitA, 2);
            logitB += __shfl_xor_sync(0xffffffffu, logitB, 2);
            float eA = __expf(logitA);         // logits bounded; no max-sub needed
            float eB = __expf(logitB);
            float sA = eA, sB = eB;
            sA += __shfl_xor_sync(0xffffffffu, sA, 4);
            sB += __shfl_xor_sync(0xffffffffu, sB, 4);
            sA += __shfl_xor_sync(0xffffffffu, sA, 8);
            sB += __shfl_xor_sync(0xffffffffu, sB, 8);
            sA += __shfl_xor_sync(0xffffffffu, sA, 16);   // = 4 * sum_j e_j (row A)
            sB += __shfl_xor_sync(0xffffffffu, sB, 16);
            if (l == 0) {
                s_red[par][0][w] = sA;
                s_red[par][1][w] = sB;
            }
            __syncthreads();
            float totA = s_red[par][0][0] + s_red[par][0][1] +
                         s_red[par][0][2] + s_red[par][0][3];
            float totB = s_red[par][1][0] + s_red[par][1][1] +
                         s_red[par][1][2] + s_red[par][1][3];
            cA = 4.f * eA / totA;
            cB = 4.f * eB / totB;
        } else {
            cA = 1.0f / 32.0f;
            cB = 1.0f / 32.0f;
        }

        const unsigned long long ccA = pack2f(cA, cA);
        const unsigned long long ccB = pack2f(cB, cB);
        a0 = ffma2(ccA, hA0, a0);
        a1 = ffma2(ccA, hA1, a1);
        a2 = ffma2(ccA, hA2, a2);
        a3 = ffma2(ccA, hA3, a3);
        a0 = ffma2(ccB, hB0, a0);
        a1 = ffma2(ccB, hB1, a1);
        a2 = ffma2(ccB, hB2, a2);
        a3 = ffma2(ccB, hB3, a3);
    }

    float* ap = &g_acc[PHASE][(b * NJ + j) * DJ + 8 * u];
    float2 v;
    v = unpack2f(a0); atomicAdd(ap + 0, v.x); atomicAdd(ap + 1, v.y);
    v = unpack2f(a1); atomicAdd(ap + 2, v.x); atomicAdd(ap + 3, v.y);
    v = unpack2f(a2); atomicAdd(ap + 4, v.x); atomicAdd(ap + 5, v.y);
    v = unpack2f(a3); atomicAdd(ap + 6, v.x); atomicAdd(ap + 7, v.y);
}

// ============================================================================
// Final squash: out = squash(g_acc[2]). grid = BB, 1024 threads; warp=j, lane=m.
// ============================================================================
__global__ void k_squash_final(float* __restrict__ out) {
    const int b = blockIdx.x;
    const int j = threadIdx.x >> 5;
    const int m = threadIdx.x & 31;
    const int idx = (b * NJ + j) * DJ + m;
    float s = g_acc[2][idx];
    float sq = s * s;
#pragma unroll
    for (int o = 16; o > 0; o >>= 1)
        sq += __shfl_xor_sync(0xffffffffu, sq, o);
    float scale = sq / ((1.f + sq) * sqrtf(sq + 1e-7f));
    out[idx] = scale * s;
}

// ============================================================================
extern "C" void kernel_launch(void* const* d_in, const int* in_sizes, int n_in,
                              void* d_out, int out_size) {
    const float* inp = (const float*)d_in[0];  // [64, 1024, 16]
    const float* W   = (const float*)d_in[1];  // [1024, 32, 16, 32]
    float* out = (float*)d_out;                // [64, 32, 32]

    const dim3 passGrid(BB, PASS_GRID_Y);

    k_hat<<<NI, 256>>>(inp, W);

    k_pass<0><<<passGrid, 128>>>();
    k_pass<1><<<passGrid, 128>>>();
    k_pass<2><<<passGrid, 128>>>();

    k_squash_final<<<BB, 1024>>>(out);
}